// round 2
// baseline (speedup 1.0000x reference)
#include <cuda_runtime.h>
#include <cstdint>

// Conditional_encoding: B=1024, T=256, V=32004, D=50, H=64
// One CTA per batch element: embed -> LSTM1 -> gather(h,c) -> LSTM2 -> gather -> FC.
// fp32 throughout; inner matvecs use packed fma.rn.f32x2 (FFMA2, 2 MACs/issue on sm_103a).

typedef unsigned long long ull;

__device__ __forceinline__ ull ffma2(ull a, ull b, ull c) {
    ull d;
    asm("fma.rn.f32x2 %0, %1, %2, %3;" : "=l"(d) : "l"(a), "l"(b), "l"(c));
    return d;
}
__device__ __forceinline__ float lo32(ull v) { return __uint_as_float((unsigned)(v & 0xFFFFFFFFull)); }
__device__ __forceinline__ float hi32(ull v) { return __uint_as_float((unsigned)(v >> 32)); }

__device__ __forceinline__ float sigm(float x) { return 1.f / (1.f + __expf(-x)); }
// tanh via exp; saturates cleanly at +/-1 for large |x| (no inf/inf NaN).
__device__ __forceinline__ float tanh_fast(float x) {
    float e = __expf(2.f * x);
    return 1.f - 2.f / (e + 1.f);
}

struct SmemT {
    float xs[2][52];   // double-buffered embedding row (50 used, padded; rows 8B-aligned)
    float hsm[64];     // current hidden state (broadcast)
    float gsm[256];    // gate preactivations i|f|g|o
    float gh[64];      // gathered h
    float gc[64];      // gathered c
    float f1[128];     // FC1 activations
    int   sidx[256];   // token indices for current sentence
    int   gidx[64];    // per-hidden-dim gather time index
};

__device__ __forceinline__ void run_lstm(
    int tid, const float* __restrict__ emb,
    const float* __restrict__ Wih, const float* __restrict__ Whh,
    const float* __restrict__ bih, const float* __restrict__ bhh,
    SmemT* sm, float cinit)
{
    // Per-thread gate-row weights, packed as (k even, k odd) f32 pairs.
    ull wih[25], whh[32];
    const ull* wr = reinterpret_cast<const ull*>(Wih + tid * 50);  // 200B offset -> 8B aligned
    #pragma unroll
    for (int k = 0; k < 25; k++) wih[k] = wr[k];
    const ull* hr = reinterpret_cast<const ull*>(Whh + tid * 64);  // 256B offset -> aligned
    #pragma unroll
    for (int k = 0; k < 32; k++) whh[k] = hr[k];

    const float bsum = bih[tid] + bhh[tid];
    float creg = cinit;
    const int myg = (tid < 64) ? sm->gidx[tid] : -1;

    // first embedding row
    if (tid < 50) sm->xs[0][tid] = emb[(size_t)sm->sidx[0] * 50 + tid];
    __syncthreads();

    for (int step = 0; step < 256; step++) {
        const int cur = step & 1;

        // Prefetch next step's embedding row (overlaps with FMA phase below).
        float xv = 0.f;
        const bool pf = (tid < 50) && (step < 255);
        if (pf) xv = __ldg(&emb[(size_t)sm->sidx[step + 1] * 50 + tid]);

        // g_t = bias + Wih[t,:]·x + Whh[t,:]·h  (packed f32x2, two accumulator chains)
        ull a0 = 0ull, a1 = 0ull;
        const ull* xp = reinterpret_cast<const ull*>(sm->xs[cur]);
        const ull* hp = reinterpret_cast<const ull*>(sm->hsm);
        #pragma unroll
        for (int k = 0; k < 25; k++) a0 = ffma2(wih[k], xp[k], a0);
        #pragma unroll
        for (int k = 0; k < 32; k++) a1 = ffma2(whh[k], hp[k], a1);
        const float g = ((lo32(a0) + hi32(a0)) + (lo32(a1) + hi32(a1))) + bsum;

        sm->gsm[tid] = g;
        if (pf) sm->xs[cur ^ 1][tid] = xv;
        __syncthreads();

        if (tid < 64) {
            const float gi = sm->gsm[tid];
            const float gf = sm->gsm[64 + tid];
            const float gg = sm->gsm[128 + tid];
            const float go = sm->gsm[192 + tid];
            creg = sigm(gf) * creg + sigm(gi) * tanh_fast(gg);
            const float h = sigm(go) * tanh_fast(creg);
            sm->hsm[tid] = h;
            if (step == myg) { sm->gh[tid] = h; sm->gc[tid] = creg; }
        }
        __syncthreads();
    }
}

__global__ void __launch_bounds__(256, 1)
cond_enc_kernel(const int* __restrict__ s1, const int* __restrict__ s2,
                const int* __restrict__ l1, const int* __restrict__ l2,
                const float* __restrict__ emb,
                const float* __restrict__ Wih1, const float* __restrict__ Whh1,
                const float* __restrict__ bih1, const float* __restrict__ bhh1,
                const float* __restrict__ Wih2, const float* __restrict__ Whh2,
                const float* __restrict__ bih2, const float* __restrict__ bhh2,
                const float* __restrict__ Wl1, const float* __restrict__ bl1,
                const float* __restrict__ Wl2, const float* __restrict__ bl2,
                float* __restrict__ out)
{
    __shared__ SmemT sm;
    const int tid = threadIdx.x;
    const int b = blockIdx.x;

    // ---------- phase 1: LSTM1 over sentence1, h0=c0=0 ----------
    sm.sidx[tid] = s1[b * 256 + tid];
    if (tid < 64) { sm.gidx[tid] = l1[b * 64 + tid]; sm.hsm[tid] = 0.f; }
    __syncthreads();
    run_lstm(tid, emb, Wih1, Whh1, bih1, bhh1, &sm, 0.f);
    __syncthreads();

    // Capture gathered state into registers before gh/gc are reused.
    const float hinit = (tid < 64) ? sm.gh[tid] : 0.f;
    const float cinit = (tid < 64) ? sm.gc[tid] : 0.f;
    __syncthreads();

    // ---------- phase 2: LSTM2 over sentence2, init = gathered state ----------
    sm.sidx[tid] = s2[b * 256 + tid];
    if (tid < 64) { sm.gidx[tid] = l2[b * 64 + tid]; sm.hsm[tid] = hinit; }
    __syncthreads();
    run_lstm(tid, emb, Wih2, Whh2, bih2, bhh2, &sm, cinit);
    __syncthreads();

    // ---------- FC head: tanh(gh @ Wl1.T + bl1) @ Wl2.T + bl2 ----------
    if (tid < 128) {
        const float* w = Wl1 + tid * 64;
        float a = bl1[tid];
        #pragma unroll
        for (int k = 0; k < 64; k++) a += w[k] * sm.gh[k];
        sm.f1[tid] = tanh_fast(a);
    }
    __syncthreads();
    if (tid < 4) {
        const float* w = Wl2 + tid * 128;
        float a = bl2[tid];
        #pragma unroll 16
        for (int k = 0; k < 128; k++) a += w[k] * sm.f1[k];
        out[b * 4 + tid] = a;
    }
}

extern "C" void kernel_launch(void* const* d_in, const int* in_sizes, int n_in,
                              void* d_out, int out_size)
{
    // metadata order:
    // 0 sentence1, 1 sentence2, 2 s1_len, 3 s2_len, 4 s1_s (unused), 5 s2_s (unused),
    // 6 emb, 7 Wih1, 8 Whh1, 9 bih1, 10 bhh1, 11 Wih2, 12 Whh2, 13 bih2, 14 bhh2,
    // 15 Wl1, 16 bl1, 17 Wl2, 18 bl2
    cond_enc_kernel<<<1024, 256>>>(
        (const int*)d_in[0], (const int*)d_in[1],
        (const int*)d_in[2], (const int*)d_in[3],
        (const float*)d_in[6],
        (const float*)d_in[7], (const float*)d_in[8],
        (const float*)d_in[9], (const float*)d_in[10],
        (const float*)d_in[11], (const float*)d_in[12],
        (const float*)d_in[13], (const float*)d_in[14],
        (const float*)d_in[15], (const float*)d_in[16],
        (const float*)d_in[17], (const float*)d_in[18],
        (float*)d_out);
}

// round 3
// speedup vs baseline: 2.2096x; 2.2096x over previous
#include <cuda_runtime.h>
#include <cstdint>

// Conditional_encoding: B=1024, T=256, V=32004, D=50, H=64
// 147 CTAs, NB=7 batch elements per CTA (1 wave on 148 SMs).
// Thread t holds gate row t's weights in registers (shared across the 7 batches);
// per step it computes gate t for all 7 batches (ILP=7 FFMA2 chains).
// Gate nonlinearities on all 256 threads via single-op tanh.approx.f32.

typedef unsigned long long ull;

#define NB  7
#define TPB 256
#define NU  (NB * 64)   // 448 hidden units per CTA
#define GRID 147        // ceil(1024 / 7)

__device__ __forceinline__ ull ffma2(ull a, ull b, ull c) {
    ull d;
    asm("fma.rn.f32x2 %0, %1, %2, %3;" : "=l"(d) : "l"(a), "l"(b), "l"(c));
    return d;
}
__device__ __forceinline__ float lo32(ull v) { return __uint_as_float((unsigned)v); }
__device__ __forceinline__ float hi32(ull v) { return __uint_as_float((unsigned)(v >> 32)); }

__device__ __forceinline__ float tanhap(float x) {
    float y;
    asm("tanh.approx.f32 %0, %1;" : "=f"(y) : "f"(x));
    return y;
}
__device__ __forceinline__ float sigm(float x) { return 0.5f * tanhap(0.5f * x) + 0.5f; }

struct SmemT {
    alignas(16) float xs[NB][2][52];   // double-buffered embedding rows (50 used, 52 pads to 16B)
    alignas(16) float hsm[NB][64];     // current hidden states
    alignas(16) float gsm[NB][256];    // gate preactivations i|f|g|o
    float gh[NB][64];                  // gathered h
    float gc[NB][64];                  // gathered c
    float f1[NB][128];                 // FC1 activations
    int   sidx[NB][256];               // token indices
    int   gidx[NB][64];                // per-hidden-dim gather time index
};

__device__ void run_lstm(int tid, const float* __restrict__ emb,
                         const float* __restrict__ Wih, const float* __restrict__ Whh,
                         const float* __restrict__ bih, const float* __restrict__ bhh,
                         SmemT* sm, float& c0, float& c1)
{
    // Gate-row weights in registers, packed (even,odd) f32 pairs.
    ull wih[25], whh[32];
    const ull* wr = reinterpret_cast<const ull*>(Wih + tid * 50);  // 200B offset -> 8B aligned
    #pragma unroll
    for (int k = 0; k < 25; k++) wih[k] = wr[k];
    const ull* hr = reinterpret_cast<const ull*>(Whh + tid * 64);  // 256B offset -> aligned
    #pragma unroll
    for (int k = 0; k < 32; k++) whh[k] = hr[k];
    const float bsum = bih[tid] + bhh[tid];

    // Gate-phase unit assignment: unit u = j*64 + hd; thread handles u=tid and u=tid+256.
    const int j0 = tid >> 6, hd0 = tid & 63;
    const int j1 = j0 + 4,   hd1 = hd0;
    const bool u1 = (tid < (NU - 256));            // tid < 192
    const int myg0 = sm->gidx[j0][hd0];
    const int myg1 = u1 ? sm->gidx[j1][hd1] : -1;

    // Embedding prefetch assignment: p in [0, NB*50) -> (j, d)
    const int  jp0 = tid / 50,        dp0 = tid % 50;
    const bool p0  = (tid < NB * 50);
    const int  jp1 = (tid + 256) / 50, dp1 = (tid + 256) % 50;
    const bool p1  = (tid + 256 < NB * 50);

    // Initial embedding rows (step 0)
    if (p0) sm->xs[jp0][0][dp0] = emb[(size_t)sm->sidx[jp0][0] * 50 + dp0];
    if (p1) sm->xs[jp1][0][dp1] = emb[(size_t)sm->sidx[jp1][0] * 50 + dp1];
    __syncthreads();

    for (int step = 0; step < 256; step++) {
        const int cur = step & 1;

        // Prefetch next step's embedding rows (latency hidden under FMA phase)
        float pv0 = 0.f, pv1 = 0.f;
        if (step < 255) {
            if (p0) pv0 = __ldg(&emb[(size_t)sm->sidx[jp0][step + 1] * 50 + dp0]);
            if (p1) pv1 = __ldg(&emb[(size_t)sm->sidx[jp1][step + 1] * 50 + dp1]);
        }

        // ---- FMA phase: gate t for all NB batches (j-inner for ILP) ----
        ull acc[NB];
        #pragma unroll
        for (int j = 0; j < NB; j++) acc[j] = 0ull;

        #pragma unroll
        for (int k2 = 0; k2 < 12; k2++) {            // x part, k = 0..47
            #pragma unroll
            for (int j = 0; j < NB; j++) {
                ulonglong2 v = *reinterpret_cast<const ulonglong2*>(&sm->xs[j][cur][k2 * 4]);
                acc[j] = ffma2(wih[2 * k2],     v.x, acc[j]);
                acc[j] = ffma2(wih[2 * k2 + 1], v.y, acc[j]);
            }
        }
        #pragma unroll
        for (int j = 0; j < NB; j++) {               // x tail, k = 48,49
            ull v = *reinterpret_cast<const ull*>(&sm->xs[j][cur][48]);
            acc[j] = ffma2(wih[24], v, acc[j]);
        }
        #pragma unroll
        for (int k2 = 0; k2 < 16; k2++) {            // h part, k = 0..63
            #pragma unroll
            for (int j = 0; j < NB; j++) {
                ulonglong2 v = *reinterpret_cast<const ulonglong2*>(&sm->hsm[j][k2 * 4]);
                acc[j] = ffma2(whh[2 * k2],     v.x, acc[j]);
                acc[j] = ffma2(whh[2 * k2 + 1], v.y, acc[j]);
            }
        }
        #pragma unroll
        for (int j = 0; j < NB; j++)
            sm->gsm[j][tid] = (lo32(acc[j]) + hi32(acc[j])) + bsum;

        if (step < 255) {
            if (p0) sm->xs[jp0][cur ^ 1][dp0] = pv0;
            if (p1) sm->xs[jp1][cur ^ 1][dp1] = pv1;
        }
        __syncthreads();

        // ---- gate phase: 448 units over 256 threads ----
        {
            float gi = sm->gsm[j0][hd0],       gf = sm->gsm[j0][64 + hd0];
            float gg = sm->gsm[j0][128 + hd0], go = sm->gsm[j0][192 + hd0];
            c0 = sigm(gf) * c0 + sigm(gi) * tanhap(gg);
            float h = sigm(go) * tanhap(c0);
            sm->hsm[j0][hd0] = h;
            if (step == myg0) { sm->gh[j0][hd0] = h; sm->gc[j0][hd0] = c0; }
        }
        if (u1) {
            float gi = sm->gsm[j1][hd1],       gf = sm->gsm[j1][64 + hd1];
            float gg = sm->gsm[j1][128 + hd1], go = sm->gsm[j1][192 + hd1];
            c1 = sigm(gf) * c1 + sigm(gi) * tanhap(gg);
            float h = sigm(go) * tanhap(c1);
            sm->hsm[j1][hd1] = h;
            if (step == myg1) { sm->gh[j1][hd1] = h; sm->gc[j1][hd1] = c1; }
        }
        __syncthreads();
    }
}

__global__ void __launch_bounds__(TPB, 1)
cond_enc_kernel(const int* __restrict__ s1, const int* __restrict__ s2,
                const int* __restrict__ l1, const int* __restrict__ l2,
                const float* __restrict__ emb,
                const float* __restrict__ Wih1, const float* __restrict__ Whh1,
                const float* __restrict__ bih1, const float* __restrict__ bhh1,
                const float* __restrict__ Wih2, const float* __restrict__ Whh2,
                const float* __restrict__ bih2, const float* __restrict__ bhh2,
                const float* __restrict__ Wl1, const float* __restrict__ bl1,
                const float* __restrict__ Wl2, const float* __restrict__ bl2,
                float* __restrict__ out)
{
    __shared__ SmemT sm;
    const int tid  = threadIdx.x;
    const int base = blockIdx.x * NB;

    // ---------- load sentence1 tokens + gather indices; zero h ----------
    #pragma unroll
    for (int j = 0; j < NB; j++) {
        int b = min(base + j, 1023);
        sm.sidx[j][tid] = s1[b * 256 + tid];
        if (tid < 64) sm.gidx[j][tid] = l1[b * 64 + tid];
    }
    for (int u = tid; u < NU; u += TPB) sm.hsm[u >> 6][u & 63] = 0.f;
    __syncthreads();

    float c0 = 0.f, c1 = 0.f;
    run_lstm(tid, emb, Wih1, Whh1, bih1, bhh1, &sm, c0, c1);

    // ---------- capture gathered state, switch to sentence2 ----------
    float h0b = sm.gh[tid >> 6][tid & 63];
    float c0b = sm.gc[tid >> 6][tid & 63];
    float h1b = 0.f, c1b = 0.f;
    if (tid < 192) {
        h1b = sm.gh[(tid >> 6) + 4][tid & 63];
        c1b = sm.gc[(tid >> 6) + 4][tid & 63];
    }
    #pragma unroll
    for (int j = 0; j < NB; j++) {
        int b = min(base + j, 1023);
        sm.sidx[j][tid] = s2[b * 256 + tid];
        if (tid < 64) sm.gidx[j][tid] = l2[b * 64 + tid];
    }
    sm.hsm[tid >> 6][tid & 63] = h0b;
    if (tid < 192) sm.hsm[(tid >> 6) + 4][tid & 63] = h1b;
    __syncthreads();

    run_lstm(tid, emb, Wih2, Whh2, bih2, bhh2, &sm, c0b, c1b);

    // ---------- FC head ----------
    for (int u = tid; u < NB * 128; u += TPB) {
        int j = u >> 7, f = u & 127;
        const float* w = Wl1 + f * 64;
        float a = bl1[f];
        #pragma unroll
        for (int k = 0; k < 64; k++) a += w[k] * sm.gh[j][k];
        sm.f1[j][f] = tanhap(a);
    }
    __syncthreads();
    if (tid < NB * 4) {
        int j = tid >> 2, o = tid & 3;
        const float* w = Wl2 + o * 128;
        float a = bl2[o];
        #pragma unroll 16
        for (int k = 0; k < 128; k++) a += w[k] * sm.f1[j][k];
        int b = base + j;
        if (b < 1024) out[b * 4 + o] = a;   // duplicated tail batches computed but not stored
    }
}

extern "C" void kernel_launch(void* const* d_in, const int* in_sizes, int n_in,
                              void* d_out, int out_size)
{
    // metadata order:
    // 0 sentence1, 1 sentence2, 2 s1_len, 3 s2_len, 4 s1_s (unused), 5 s2_s (unused),
    // 6 emb, 7 Wih1, 8 Whh1, 9 bih1, 10 bhh1, 11 Wih2, 12 Whh2, 13 bih2, 14 bhh2,
    // 15 Wl1, 16 bl1, 17 Wl2, 18 bl2
    cond_enc_kernel<<<GRID, TPB>>>(
        (const int*)d_in[0], (const int*)d_in[1],
        (const int*)d_in[2], (const int*)d_in[3],
        (const float*)d_in[6],
        (const float*)d_in[7], (const float*)d_in[8],
        (const float*)d_in[9], (const float*)d_in[10],
        (const float*)d_in[11], (const float*)d_in[12],
        (const float*)d_in[13], (const float*)d_in[14],
        (const float*)d_in[15], (const float*)d_in[16],
        (const float*)d_in[17], (const float*)d_in[18],
        (float*)d_out);
}

// round 4
// speedup vs baseline: 2.8514x; 1.2905x over previous
#include <cuda_runtime.h>
#include <cstdint>

// Conditional_encoding: B=1024, T=256, V=32004, D=50, H=64
// Stage 1: precompute GX[layer][v][256] = Wih@emb[v] + bih + bhh  (token-indexed gate table,
//          32.8 MB/layer, L2-resident). Removes the x-projection from the recurrence.
// Stage 2: 147 CTAs x 512 threads, NB=7 batches/CTA (1 wave). Thread pair (row, half)
//          computes half of gate row `row` for 7 batches; partials summed in smem.

typedef unsigned long long ull;

#define NB   7
#define TPB  512
#define NU   (NB * 64)      // 448 units per CTA
#define GRID 147            // ceil(1024/7)
#define VOC  32004

__device__ float GXT[2][(size_t)VOC * 256];   // token-indexed gate tables (layer 1, 2)

__device__ __forceinline__ ull ffma2(ull a, ull b, ull c) {
    ull d;
    asm("fma.rn.f32x2 %0, %1, %2, %3;" : "=l"(d) : "l"(a), "l"(b), "l"(c));
    return d;
}
__device__ __forceinline__ float lo32(ull v) { return __uint_as_float((unsigned)v); }
__device__ __forceinline__ float hi32(ull v) { return __uint_as_float((unsigned)(v >> 32)); }
__device__ __forceinline__ float tanhap(float x) {
    float y;
    asm("tanh.approx.f32 %0, %1;" : "=f"(y) : "f"(x));
    return y;
}
__device__ __forceinline__ float sigm(float x) { return 0.5f * tanhap(0.5f * x) + 0.5f; }

// ---------------- stage 1: vocab gate-table precompute ----------------
#define PC_CHUNK 217   // ceil(32004/148)

__global__ void __launch_bounds__(256)
precompute_gx(const float* __restrict__ emb,
              const float* __restrict__ Wih1, const float* __restrict__ bih1,
              const float* __restrict__ bhh1,
              const float* __restrict__ Wih2, const float* __restrict__ bih2,
              const float* __restrict__ bhh2)
{
    const int layer = blockIdx.y;
    const float* __restrict__ Wih = layer ? Wih2 : Wih1;
    const float* __restrict__ bi  = layer ? bih2 : bih1;
    const float* __restrict__ bh  = layer ? bhh2 : bhh1;
    float* __restrict__ GX = GXT[layer];

    const int tid = threadIdx.x;          // gate row
    ull wih[25];
    const ull* wr = reinterpret_cast<const ull*>(Wih + tid * 50);  // 200B offset, 8B aligned
    #pragma unroll
    for (int k = 0; k < 25; k++) wih[k] = wr[k];
    const float bsum = bi[tid] + bh[tid];

    __shared__ __align__(16) float xb[2][52];
    const int v0 = blockIdx.x * PC_CHUNK;
    const int v1 = min(v0 + PC_CHUNK, VOC);
    if (v0 >= VOC) return;

    if (tid < 50) xb[0][tid] = emb[(size_t)v0 * 50 + tid];
    __syncthreads();

    for (int v = v0; v < v1; v++) {
        const int cur = (v - v0) & 1;
        float xr = 0.f;
        const bool pf = (tid < 50) && (v + 1 < v1);
        if (pf) xr = __ldg(&emb[(size_t)(v + 1) * 50 + tid]);

        ull a = 0ull;
        const ull* xp = reinterpret_cast<const ull*>(xb[cur]);
        #pragma unroll
        for (int k = 0; k < 25; k++) a = ffma2(wih[k], xp[k], a);
        GX[(size_t)v * 256 + tid] = (lo32(a) + hi32(a)) + bsum;

        if (pf) xb[cur ^ 1][tid] = xr;
        __syncthreads();
    }
}

// ---------------- stage 2: fused recurrence ----------------
struct SmemT {
    alignas(16) float hsm[NB][64];        // current hidden states
    alignas(16) float psum[2][NB][256];   // gate partials (half 0 includes gx + bias)
    float gh[NB][64];                     // gathered h
    float gc[NB][64];                     // gathered c
    float f1[NB][128];                    // FC1 activations
    int   sidx[NB][256];                  // token indices
    int   gidx[NB][64];                   // gather time index per hidden dim
};

__device__ void run_lstm(int tid, const float* __restrict__ gx,
                         const float* __restrict__ Whh, SmemT* sm, float& c)
{
    const int half = tid >> 8;            // which 32-wide K half
    const int row  = tid & 255;           // gate row

    ull whh[16];
    const ull* hr = reinterpret_cast<const ull*>(Whh + row * 64 + half * 32);  // 128B-mult offset
    #pragma unroll
    for (int k = 0; k < 16; k++) whh[k] = hr[k];

    const int  j0 = tid >> 6, hd0 = tid & 63;     // gate-phase unit (tid < 448)
    const bool gu = (tid < NU);
    const int  myg = gu ? sm->gidx[j0][hd0] : -1;

    // gx for step 0 (half 0 only; one coalesced 128B line per warp per batch)
    float gxv[NB];
    if (half == 0) {
        #pragma unroll
        for (int j = 0; j < NB; j++)
            gxv[j] = __ldg(&gx[(size_t)sm->sidx[j][0] * 256 + row]);
    }

    for (int step = 0; step < 256; step++) {
        // prefetch next step's gx (L2-resident table; hidden under FMA phase)
        float nxt[NB];
        if (half == 0 && step < 255) {
            #pragma unroll
            for (int j = 0; j < NB; j++)
                nxt[j] = __ldg(&gx[(size_t)sm->sidx[j][step + 1] * 256 + row]);
        }

        // ---- FMA phase: half of Whh[row]·h for all 7 batches ----
        ull acc[NB];
        #pragma unroll
        for (int j = 0; j < NB; j++) acc[j] = 0ull;
        #pragma unroll
        for (int k2 = 0; k2 < 8; k2++) {
            #pragma unroll
            for (int j = 0; j < NB; j++) {
                ulonglong2 v = *reinterpret_cast<const ulonglong2*>(
                    &sm->hsm[j][half * 32 + k2 * 4]);
                acc[j] = ffma2(whh[2 * k2],     v.x, acc[j]);
                acc[j] = ffma2(whh[2 * k2 + 1], v.y, acc[j]);
            }
        }
        if (half == 0) {
            #pragma unroll
            for (int j = 0; j < NB; j++)
                sm->psum[0][j][row] = (lo32(acc[j]) + hi32(acc[j])) + gxv[j];
            if (step < 255) {
                #pragma unroll
                for (int j = 0; j < NB; j++) gxv[j] = nxt[j];
            }
        } else {
            #pragma unroll
            for (int j = 0; j < NB; j++)
                sm->psum[1][j][row] = lo32(acc[j]) + hi32(acc[j]);
        }
        __syncthreads();

        // ---- gate phase: 448 units on threads 0..447 ----
        if (gu) {
            float gi = sm->psum[0][j0][hd0]       + sm->psum[1][j0][hd0];
            float gf = sm->psum[0][j0][64 + hd0]  + sm->psum[1][j0][64 + hd0];
            float gg = sm->psum[0][j0][128 + hd0] + sm->psum[1][j0][128 + hd0];
            float go = sm->psum[0][j0][192 + hd0] + sm->psum[1][j0][192 + hd0];
            c = sigm(gf) * c + sigm(gi) * tanhap(gg);
            float h = sigm(go) * tanhap(c);
            sm->hsm[j0][hd0] = h;
            if (step == myg) { sm->gh[j0][hd0] = h; sm->gc[j0][hd0] = c; }
        }
        __syncthreads();
    }
}

__global__ void __launch_bounds__(TPB, 1)
cond_enc_kernel(const int* __restrict__ s1, const int* __restrict__ s2,
                const int* __restrict__ l1, const int* __restrict__ l2,
                const float* __restrict__ Whh1, const float* __restrict__ Whh2,
                const float* __restrict__ Wl1, const float* __restrict__ bl1,
                const float* __restrict__ Wl2, const float* __restrict__ bl2,
                float* __restrict__ out)
{
    __shared__ SmemT sm;
    const int tid  = threadIdx.x;
    const int base = blockIdx.x * NB;
    const int j0 = tid >> 6, hd0 = tid & 63;

    // ---------- sentence1 setup ----------
    for (int i = tid; i < NB * 256; i += TPB) {
        int j = i >> 8, t = i & 255;
        int b = min(base + j, 1023);
        sm.sidx[j][t] = s1[b * 256 + t];
    }
    if (tid < NU) {
        int b = min(base + j0, 1023);
        sm.gidx[j0][hd0] = l1[b * 64 + hd0];
        sm.hsm[j0][hd0]  = 0.f;
    }
    __syncthreads();

    float c = 0.f;
    run_lstm(tid, GXT[0], Whh1, &sm, c);

    // ---------- switch to sentence2 (init = gathered state) ----------
    float hinit = 0.f;
    if (tid < NU) { hinit = sm.gh[j0][hd0]; c = sm.gc[j0][hd0]; }
    __syncthreads();   // gh/gc reads done before any reuse; sidx rewrite below
    for (int i = tid; i < NB * 256; i += TPB) {
        int j = i >> 8, t = i & 255;
        int b = min(base + j, 1023);
        sm.sidx[j][t] = s2[b * 256 + t];
    }
    if (tid < NU) {
        int b = min(base + j0, 1023);
        sm.gidx[j0][hd0] = l2[b * 64 + hd0];
        sm.hsm[j0][hd0]  = hinit;
    }
    __syncthreads();

    run_lstm(tid, GXT[1], Whh2, &sm, c);

    // ---------- FC head ----------
    for (int u = tid; u < NB * 128; u += TPB) {
        int j = u >> 7, f = u & 127;
        const float* w = Wl1 + f * 64;
        float a = bl1[f];
        #pragma unroll
        for (int k = 0; k < 64; k++) a += w[k] * sm.gh[j][k];
        sm.f1[j][f] = tanhap(a);
    }
    __syncthreads();
    if (tid < NB * 4) {
        int j = tid >> 2, o = tid & 3;
        const float* w = Wl2 + o * 128;
        float a = bl2[o];
        #pragma unroll 16
        for (int k = 0; k < 128; k++) a += w[k] * sm.f1[j][k];
        int b = base + j;
        if (b < 1024) out[b * 4 + o] = a;
    }
}

extern "C" void kernel_launch(void* const* d_in, const int* in_sizes, int n_in,
                              void* d_out, int out_size)
{
    // metadata order:
    // 0 sentence1, 1 sentence2, 2 s1_len, 3 s2_len, 4 s1_s, 5 s2_s,
    // 6 emb, 7 Wih1, 8 Whh1, 9 bih1, 10 bhh1, 11 Wih2, 12 Whh2, 13 bih2, 14 bhh2,
    // 15 Wl1, 16 bl1, 17 Wl2, 18 bl2
    precompute_gx<<<dim3(148, 2), 256>>>(
        (const float*)d_in[6],
        (const float*)d_in[7], (const float*)d_in[9], (const float*)d_in[10],
        (const float*)d_in[11], (const float*)d_in[13], (const float*)d_in[14]);

    cond_enc_kernel<<<GRID, TPB>>>(
        (const int*)d_in[0], (const int*)d_in[1],
        (const int*)d_in[2], (const int*)d_in[3],
        (const float*)d_in[8], (const float*)d_in[12],
        (const float*)d_in[15], (const float*)d_in[16],
        (const float*)d_in[17], (const float*)d_in[18],
        (float*)d_out);
}

// round 6
// speedup vs baseline: 3.4446x; 1.2080x over previous
#include <cuda_runtime.h>
#include <cstdint>

// Conditional_encoding: B=1024, T=256, V=32004, D=50, H=64
// Stage 1: GX[layer][v][256] = Wih@emb[v] + bih + bhh (token gate table, L2-resident).
// Stage 2: 147 CTAs x 512 threads, NB=7 batches. CTA split into 2 independent groups
//          (batches 0-3 / 4-6) with private named barriers so their tails overlap.
//          Thread owns one FULL gate row (64 weights in regs) -> psum is a complete dot.

typedef unsigned long long ull;

#define NB   7
#define TPB  512
#define GRID 147
#define VOC  32004

__device__ float GXT[2][(size_t)VOC * 256];

__device__ __forceinline__ ull ffma2(ull a, ull b, ull c) {
    ull d;
    asm("fma.rn.f32x2 %0, %1, %2, %3;" : "=l"(d) : "l"(a), "l"(b), "l"(c));
    return d;
}
__device__ __forceinline__ float lo32(ull v) { return __uint_as_float((unsigned)v); }
__device__ __forceinline__ float hi32(ull v) { return __uint_as_float((unsigned)(v >> 32)); }
__device__ __forceinline__ float tanhap(float x) {
    float y;
    asm("tanh.approx.f32 %0, %1;" : "=f"(y) : "f"(x));
    return y;
}
__device__ __forceinline__ float sigm(float x) { return 0.5f * tanhap(0.5f * x) + 0.5f; }
__device__ __forceinline__ void barsync(int id) {
    asm volatile("bar.sync %0, %1;" :: "r"(id), "r"(256) : "memory");
}

// ---------------- stage 1: vocab gate-table precompute ----------------
#define PC_CHUNK 54   // 593 * 54 >= 32004

__global__ void __launch_bounds__(256)
precompute_gx(const float* __restrict__ emb,
              const float* __restrict__ Wih1, const float* __restrict__ bih1,
              const float* __restrict__ bhh1,
              const float* __restrict__ Wih2, const float* __restrict__ bih2,
              const float* __restrict__ bhh2)
{
    const int layer = blockIdx.y;
    const float* __restrict__ Wih = layer ? Wih2 : Wih1;
    const float* __restrict__ bi  = layer ? bih2 : bih1;
    const float* __restrict__ bh  = layer ? bhh2 : bhh1;
    float* __restrict__ GX = GXT[layer];

    const int tid = threadIdx.x;   // gate row
    ull wih[25];
    const ull* wr = reinterpret_cast<const ull*>(Wih + tid * 50);
    #pragma unroll
    for (int k = 0; k < 25; k++) wih[k] = wr[k];
    const float bsum = bi[tid] + bh[tid];

    __shared__ __align__(16) float xb[2][52];
    const int v0 = blockIdx.x * PC_CHUNK;
    const int v1 = min(v0 + PC_CHUNK, VOC);
    if (v0 >= VOC) return;

    if (tid < 50) xb[0][tid] = emb[(size_t)v0 * 50 + tid];
    __syncthreads();

    for (int v = v0; v < v1; v++) {
        const int cur = (v - v0) & 1;
        float xr = 0.f;
        const bool pf = (tid < 50) && (v + 1 < v1);
        if (pf) xr = __ldg(&emb[(size_t)(v + 1) * 50 + tid]);

        ull a = 0ull;
        const ull* xp = reinterpret_cast<const ull*>(xb[cur]);
        #pragma unroll
        for (int k = 0; k < 25; k++) a = ffma2(wih[k], xp[k], a);
        GX[(size_t)v * 256 + tid] = (lo32(a) + hi32(a)) + bsum;

        if (pf) xb[cur ^ 1][tid] = xr;
        __syncthreads();
    }
}

// ---------------- stage 2: fused recurrence ----------------
struct SmemT {
    alignas(16) float hsm[NB][64];     // hidden states (group-partitioned by j)
    alignas(16) float psum[NB][256];   // full gate preacts incl. gx
    float gh[NB][64];
    float gc[NB][64];
    float f1[NB][128];
    int   sidx[NB][256];
    int   gidx[NB][64];
};

// One group: GC batches starting at jbase, 256 threads, private named barrier.
template<int GC>
__device__ void run_lstm_grp(int r, int jbase, int barid,
                             const float* __restrict__ gx,
                             const float* __restrict__ Whh,
                             SmemT* sm, float& c)
{
    ull whh[32];
    const ull* hr = reinterpret_cast<const ull*>(Whh + r * 64);
    #pragma unroll
    for (int k = 0; k < 32; k++) whh[k] = hr[k];

    const bool gu = (r < GC * 64);
    const int  jg = jbase + ((r >> 6) & 3);
    const int  hd = r & 63;
    const int  myg = gu ? sm->gidx[jg][hd] : -1;

    float gxv[GC];
    #pragma unroll
    for (int j = 0; j < GC; j++)
        gxv[j] = __ldg(&gx[(size_t)sm->sidx[jbase + j][0] * 256 + r]);

    for (int step = 0; step < 256; step++) {
        // prefetch next gx rows (L2 table), hidden under FMA phase
        float nxt[GC];
        if (step < 255) {
            #pragma unroll
            for (int j = 0; j < GC; j++)
                nxt[j] = __ldg(&gx[(size_t)sm->sidx[jbase + j][step + 1] * 256 + r]);
        }

        // ---- FMA: full row r dot h, GC independent chains ----
        ull acc[GC];
        #pragma unroll
        for (int j = 0; j < GC; j++) acc[j] = 0ull;
        #pragma unroll
        for (int k2 = 0; k2 < 16; k2++) {
            #pragma unroll
            for (int j = 0; j < GC; j++) {
                ulonglong2 v = *reinterpret_cast<const ulonglong2*>(
                    &sm->hsm[jbase + j][k2 * 4]);
                acc[j] = ffma2(whh[2 * k2],     v.x, acc[j]);
                acc[j] = ffma2(whh[2 * k2 + 1], v.y, acc[j]);
            }
        }
        #pragma unroll
        for (int j = 0; j < GC; j++)
            sm->psum[jbase + j][r] = (lo32(acc[j]) + hi32(acc[j])) + gxv[j];
        if (step < 255) {
            #pragma unroll
            for (int j = 0; j < GC; j++) gxv[j] = nxt[j];
        }
        barsync(barid);

        // ---- gate: one unit per thread ----
        if (gu) {
            float gi = sm->psum[jg][hd];
            float gf = sm->psum[jg][64 + hd];
            float gg = sm->psum[jg][128 + hd];
            float go = sm->psum[jg][192 + hd];
            c = sigm(gf) * c + sigm(gi) * tanhap(gg);
            float h = sigm(go) * tanhap(c);
            sm->hsm[jg][hd] = h;
            if (step == myg) { sm->gh[jg][hd] = h; sm->gc[jg][hd] = c; }
        }
        barsync(barid);
    }
}

__global__ void __launch_bounds__(TPB, 1)
cond_enc_kernel(const int* __restrict__ s1, const int* __restrict__ s2,
                const int* __restrict__ l1, const int* __restrict__ l2,
                const float* __restrict__ Whh1, const float* __restrict__ Whh2,
                const float* __restrict__ Wl1, const float* __restrict__ bl1,
                const float* __restrict__ Wl2, const float* __restrict__ bl2,
                float* __restrict__ out)
{
    __shared__ SmemT sm;
    const int tid  = threadIdx.x;
    const int base = blockIdx.x * NB;
    const int g = tid >> 8;        // group 0: batches 0-3, group 1: batches 4-6
    const int r = tid & 255;       // gate row within group

    const bool gu = (g == 0) ? true : (r < 192);
    const int  jg = (g == 0) ? (r >> 6) : 4 + ((r >> 6) & 3);
    const int  hd = r & 63;

    // ---------- sentence1 setup ----------
    for (int i = tid; i < NB * 256; i += TPB) {
        int j = i >> 8, t = i & 255;
        int b = min(base + j, 1023);
        sm.sidx[j][t] = s1[b * 256 + t];
    }
    if (gu) {
        int b = min(base + jg, 1023);
        sm.gidx[jg][hd] = l1[b * 64 + hd];
        sm.hsm[jg][hd]  = 0.f;
    }
    __syncthreads();

    float c = 0.f;
    if (g == 0) run_lstm_grp<4>(r, 0, 1, GXT[0], Whh1, &sm, c);
    else        run_lstm_grp<3>(r, 4, 2, GXT[0], Whh1, &sm, c);
    __syncthreads();

    // ---------- capture gathered state, switch to sentence2 ----------
    float hinit = gu ? sm.gh[jg][hd] : 0.f;
    float cinit = gu ? sm.gc[jg][hd] : 0.f;
    __syncthreads();
    for (int i = tid; i < NB * 256; i += TPB) {
        int j = i >> 8, t = i & 255;
        int b = min(base + j, 1023);
        sm.sidx[j][t] = s2[b * 256 + t];
    }
    if (gu) {
        int b = min(base + jg, 1023);
        sm.gidx[jg][hd] = l2[b * 64 + hd];
        sm.hsm[jg][hd]  = hinit;
    }
    __syncthreads();

    c = cinit;
    if (g == 0) run_lstm_grp<4>(r, 0, 1, GXT[1], Whh2, &sm, c);
    else        run_lstm_grp<3>(r, 4, 2, GXT[1], Whh2, &sm, c);
    __syncthreads();

    // ---------- FC head ----------
    for (int u = tid; u < NB * 128; u += TPB) {
        int j = u >> 7, f = u & 127;
        const float* w = Wl1 + f * 64;
        float a = bl1[f];
        #pragma unroll
        for (int k = 0; k < 64; k++) a += w[k] * sm.gh[j][k];
        sm.f1[j][f] = tanhap(a);
    }
    __syncthreads();
    if (tid < NB * 4) {
        int j = tid >> 2, o = tid & 3;
        const float* w = Wl2 + o * 128;
        float a = bl2[o];
        #pragma unroll 16
        for (int k = 0; k < 128; k++) a += w[k] * sm.f1[j][k];
        int b = base + j;
        if (b < 1024) out[b * 4 + o] = a;
    }
}

extern "C" void kernel_launch(void* const* d_in, const int* in_sizes, int n_in,
                              void* d_out, int out_size)
{
    // 0 s1, 1 s2, 2 s1_len, 3 s2_len, 4 s1_s, 5 s2_s, 6 emb,
    // 7 Wih1, 8 Whh1, 9 bih1, 10 bhh1, 11 Wih2, 12 Whh2, 13 bih2, 14 bhh2,
    // 15 Wl1, 16 bl1, 17 Wl2, 18 bl2
    precompute_gx<<<dim3(593, 2), 256>>>(
        (const float*)d_in[6],
        (const float*)d_in[7], (const float*)d_in[9], (const float*)d_in[10],
        (const float*)d_in[11], (const float*)d_in[13], (const float*)d_in[14]);

    cond_enc_kernel<<<GRID, TPB>>>(
        (const int*)d_in[0], (const int*)d_in[1],
        (const int*)d_in[2], (const int*)d_in[3],
        (const float*)d_in[8], (const float*)d_in[12],
        (const float*)d_in[15], (const float*)d_in[16],
        (const float*)d_in[17], (const float*)d_in[18],
        (float*)d_out);
}

// round 7
// speedup vs baseline: 4.7876x; 1.3899x over previous
#include <cuda_runtime.h>
#include <cuda_fp16.h>
#include <cstdint>

// Conditional_encoding: B=1024, T=256, V=32004, D=50, H=64
// Stage 1: GX[layer][v][256] = Wih@emb[v] + bih + bhh (token gate table, L2-resident).
// Stage 2: 147 CTAs x 512 threads, NB=7. Recurrence h@Whh^T on tensor cores:
//   mma.sync.m16n8k16 fp16 with hi/lo split (3 passes) => fp32-accurate.
//   M=16 (7 batches + 9 zero rows), K=64 (4 tiles), N=256 (16 cols/warp).
//   B-fragments (weights) live in registers; A built from packed fp16 h in smem.

typedef unsigned long long ull;

#define NB   7
#define TPB  512
#define GRID 147
#define VOC  32004

__device__ float GXT[2][(size_t)VOC * 256];

__device__ __forceinline__ ull ffma2(ull a, ull b, ull c) {
    ull d;
    asm("fma.rn.f32x2 %0, %1, %2, %3;" : "=l"(d) : "l"(a), "l"(b), "l"(c));
    return d;
}
__device__ __forceinline__ float lo32(ull v) { return __uint_as_float((unsigned)v); }
__device__ __forceinline__ float hi32(ull v) { return __uint_as_float((unsigned)(v >> 32)); }
__device__ __forceinline__ float tanhap(float x) {
    float y;
    asm("tanh.approx.f32 %0, %1;" : "=f"(y) : "f"(x));
    return y;
}
__device__ __forceinline__ float sigm(float x) { return 0.5f * tanhap(0.5f * x) + 0.5f; }

__device__ __forceinline__ void mma16816(float& c0, float& c1, float& c2, float& c3,
                                         unsigned a0, unsigned a1, unsigned a2, unsigned a3,
                                         unsigned b0, unsigned b1) {
    asm volatile("mma.sync.aligned.m16n8k16.row.col.f32.f16.f16.f32 "
                 "{%0,%1,%2,%3}, {%4,%5,%6,%7}, {%8,%9}, {%0,%1,%2,%3};"
                 : "+f"(c0), "+f"(c1), "+f"(c2), "+f"(c3)
                 : "r"(a0), "r"(a1), "r"(a2), "r"(a3), "r"(b0), "r"(b1));
}
__device__ __forceinline__ unsigned h2u(__half2 h) { return *reinterpret_cast<unsigned*>(&h); }

// ---------------- stage 1: vocab gate-table precompute (4 tokens / iter) ----------------
#define PCT 4
#define PCI 14
#define PCC (PCT * PCI)          // 56 tokens per block
#define PCG ((VOC + PCC - 1) / PCC)   // 572

__global__ void __launch_bounds__(256)
precompute_gx(const float* __restrict__ emb,
              const float* __restrict__ Wih1, const float* __restrict__ bih1,
              const float* __restrict__ bhh1,
              const float* __restrict__ Wih2, const float* __restrict__ bih2,
              const float* __restrict__ bhh2)
{
    const int layer = blockIdx.y;
    const float* __restrict__ Wih = layer ? Wih2 : Wih1;
    const float* __restrict__ bi  = layer ? bih2 : bih1;
    const float* __restrict__ bh  = layer ? bhh2 : bhh1;
    float* __restrict__ GX = GXT[layer];

    const int tid = threadIdx.x;   // gate row
    ull wih[25];
    const ull* wr = reinterpret_cast<const ull*>(Wih + tid * 50);
    #pragma unroll
    for (int k = 0; k < 25; k++) wih[k] = wr[k];
    const float bsum = bi[tid] + bh[tid];

    __shared__ __align__(16) float xb[2][PCT][52];
    const int v0 = blockIdx.x * PCC;
    const int lt = tid / 50, ld = tid % 50;
    const bool lp = tid < PCT * 50;

    if (lp) {
        int v = min(v0 + lt, VOC - 1);
        xb[0][lt][ld] = __ldg(&emb[(size_t)v * 50 + ld]);
    }
    __syncthreads();

    for (int it = 0; it < PCI; it++) {
        const int cur = it & 1;
        const int vb = v0 + it * PCT;
        float pf = 0.f;
        if (lp && it + 1 < PCI) {
            int v = min(vb + PCT + lt, VOC - 1);
            pf = __ldg(&emb[(size_t)v * 50 + ld]);
        }
        ull acc[PCT] = {0ull, 0ull, 0ull, 0ull};
        #pragma unroll
        for (int k = 0; k < 25; k++) {
            #pragma unroll
            for (int t = 0; t < PCT; t++)
                acc[t] = ffma2(wih[k], *reinterpret_cast<const ull*>(&xb[cur][t][k * 2]), acc[t]);
        }
        #pragma unroll
        for (int t = 0; t < PCT; t++) {
            int v = vb + t;
            if (v < VOC) GX[(size_t)v * 256 + tid] = (lo32(acc[t]) + hi32(acc[t])) + bsum;
        }
        if (lp && it + 1 < PCI) xb[cur ^ 1][lt][ld] = pf;
        __syncthreads();
    }
}

// ---------------- stage 2: fused recurrence on tensor cores ----------------
#define HPS 72    // hpack row stride in halves (36 words -> conflict-free A-frag loads)
#define PSS 258   // psum row stride in floats

struct SmemT {
    __half hhi[NB][HPS];       // packed fp16 hi of h
    __half hlo[NB][HPS];       // packed fp16 lo of h
    float  psum[NB][PSS];      // gate preacts (mma output)
    float  gh[NB][64];
    float  gc[NB][64];
    float  f1[NB][128];
    int    sidx[NB][256];
    int    gidx[NB][64];
};

__device__ void run_lstm(int tid, const float* __restrict__ gx,
                         const float* __restrict__ Whh, SmemT* sm, float& c)
{
    const int warp = tid >> 5, lane = tid & 31;
    const int grp = lane >> 2, tig = lane & 3;

    // ---- B fragments (weights), hi/lo split, built once per layer ----
    unsigned bhf[2][4][2], blf[2][4][2];
    #pragma unroll
    for (int nt = 0; nt < 2; nt++) {
        #pragma unroll
        for (int kt = 0; kt < 4; kt++) {
            int n = warp * 16 + nt * 8 + grp;
            int k = kt * 16 + tig * 2;
            float2 w0 = *reinterpret_cast<const float2*>(&Whh[n * 64 + k]);
            float2 w1 = *reinterpret_cast<const float2*>(&Whh[n * 64 + k + 8]);
            __half2 h0 = __floats2half2_rn(w0.x, w0.y);
            __half2 h1 = __floats2half2_rn(w1.x, w1.y);
            float2 r0 = __half22float2(h0), r1 = __half22float2(h1);
            __half2 l0 = __floats2half2_rn(w0.x - r0.x, w0.y - r0.y);
            __half2 l1 = __floats2half2_rn(w1.x - r1.x, w1.y - r1.y);
            bhf[nt][kt][0] = h2u(h0); bhf[nt][kt][1] = h2u(h1);
            blf[nt][kt][0] = h2u(l0); blf[nt][kt][1] = h2u(l1);
        }
    }

    const bool gu = tid < NB * 64;
    const int  j = tid >> 6, hd = tid & 63;
    const int  myg = gu ? sm->gidx[j][hd] : -1;

    float g0 = 0.f, g1 = 0.f, g2 = 0.f, g3 = 0.f;
    if (gu) {
        const float* p = gx + (size_t)sm->sidx[j][0] * 256 + hd;
        g0 = __ldg(p); g1 = __ldg(p + 64); g2 = __ldg(p + 128); g3 = __ldg(p + 192);
    }

    for (int step = 0; step < 256; step++) {
        // ---- A fragments from packed h (rows >= 7 are zero) ----
        unsigned ah[4][2], al[4][2];
        if (grp < NB) {
            #pragma unroll
            for (int kt = 0; kt < 4; kt++) {
                int off = kt * 16 + tig * 2;
                ah[kt][0] = *reinterpret_cast<const unsigned*>(&sm->hhi[grp][off]);
                ah[kt][1] = *reinterpret_cast<const unsigned*>(&sm->hhi[grp][off + 8]);
                al[kt][0] = *reinterpret_cast<const unsigned*>(&sm->hlo[grp][off]);
                al[kt][1] = *reinterpret_cast<const unsigned*>(&sm->hlo[grp][off + 8]);
            }
        } else {
            #pragma unroll
            for (int kt = 0; kt < 4; kt++) {
                ah[kt][0] = ah[kt][1] = 0u; al[kt][0] = al[kt][1] = 0u;
            }
        }

        // 4 accumulation chains (2 n-tiles x 2 k-halves) for ILP.
        float cA0 = 0.f, cA1 = 0.f, cA2 = 0.f, cA3 = 0.f;
        float cB0 = 0.f, cB1 = 0.f, cB2 = 0.f, cB3 = 0.f;
        float cC0 = 0.f, cC1 = 0.f, cC2 = 0.f, cC3 = 0.f;
        float cD0 = 0.f, cD1 = 0.f, cD2 = 0.f, cD3 = 0.f;
        #pragma unroll
        for (int kh = 0; kh < 2; kh++) {
            int k0 = kh * 2, k1 = kh * 2 + 1;
            float &x0 = kh ? cB0 : cA0, &x1 = kh ? cB1 : cA1,
                  &x2 = kh ? cB2 : cA2, &x3 = kh ? cB3 : cA3;
            float &y0 = kh ? cD0 : cC0, &y1 = kh ? cD1 : cC1,
                  &y2 = kh ? cD2 : cC2, &y3 = kh ? cD3 : cC3;
            #pragma unroll
            for (int kk = 0; kk < 2; kk++) {
                int kt = kk ? k1 : k0;
                mma16816(x0, x1, x2, x3, ah[kt][0], 0u, ah[kt][1], 0u, bhf[0][kt][0], bhf[0][kt][1]);
                mma16816(y0, y1, y2, y3, ah[kt][0], 0u, ah[kt][1], 0u, bhf[1][kt][0], bhf[1][kt][1]);
                mma16816(x0, x1, x2, x3, al[kt][0], 0u, al[kt][1], 0u, bhf[0][kt][0], bhf[0][kt][1]);
                mma16816(y0, y1, y2, y3, al[kt][0], 0u, al[kt][1], 0u, bhf[1][kt][0], bhf[1][kt][1]);
                mma16816(x0, x1, x2, x3, ah[kt][0], 0u, ah[kt][1], 0u, blf[0][kt][0], blf[0][kt][1]);
                mma16816(y0, y1, y2, y3, ah[kt][0], 0u, ah[kt][1], 0u, blf[1][kt][0], blf[1][kt][1]);
            }
        }
        if (grp < NB) {
            int col = warp * 16 + tig * 2;
            *reinterpret_cast<float2*>(&sm->psum[grp][col])     = make_float2(cA0 + cB0, cA1 + cB1);
            *reinterpret_cast<float2*>(&sm->psum[grp][col + 8]) = make_float2(cC0 + cD0, cC1 + cD1);
        }
        __syncthreads();

        // ---- gate phase (threads 0..447) ----
        if (gu) {
            float gi = sm->psum[j][hd]       + g0;
            float gf = sm->psum[j][64 + hd]  + g1;
            float gg = sm->psum[j][128 + hd] + g2;
            float go = sm->psum[j][192 + hd] + g3;
            c = sigm(gf) * c + sigm(gi) * tanhap(gg);
            float h = sigm(go) * tanhap(c);
            __half hh = __float2half_rn(h);
            sm->hhi[j][hd] = hh;
            sm->hlo[j][hd] = __float2half_rn(h - __half2float(hh));
            if (step == myg) { sm->gh[j][hd] = h; sm->gc[j][hd] = c; }
            if (step < 255) {
                const float* p = gx + (size_t)sm->sidx[j][step + 1] * 256 + hd;
                g0 = __ldg(p); g1 = __ldg(p + 64); g2 = __ldg(p + 128); g3 = __ldg(p + 192);
            }
        }
        __syncthreads();
    }
}

__global__ void __launch_bounds__(TPB, 1)
cond_enc_kernel(const int* __restrict__ s1, const int* __restrict__ s2,
                const int* __restrict__ l1, const int* __restrict__ l2,
                const float* __restrict__ Whh1, const float* __restrict__ Whh2,
                const float* __restrict__ Wl1, const float* __restrict__ bl1,
                const float* __restrict__ Wl2, const float* __restrict__ bl2,
                float* __restrict__ out)
{
    __shared__ SmemT sm;
    const int tid  = threadIdx.x;
    const int base = blockIdx.x * NB;
    const bool gu = tid < NB * 64;
    const int  j = tid >> 6, hd = tid & 63;

    // ---------- sentence1 setup ----------
    for (int i = tid; i < NB * 256; i += TPB) {
        int jj = i >> 8, t = i & 255;
        int b = min(base + jj, 1023);
        sm.sidx[jj][t] = s1[b * 256 + t];
    }
    if (gu) {
        int b = min(base + j, 1023);
        sm.gidx[j][hd] = l1[b * 64 + hd];
        sm.hhi[j][hd] = __float2half_rn(0.f);
        sm.hlo[j][hd] = __float2half_rn(0.f);
    }
    __syncthreads();

    float c = 0.f;
    run_lstm(tid, GXT[0], Whh1, &sm, c);
    __syncthreads();

    // ---------- capture gathered state, switch to sentence2 ----------
    float hinit = gu ? sm.gh[j][hd] : 0.f;
    float cinit = gu ? sm.gc[j][hd] : 0.f;
    __syncthreads();
    for (int i = tid; i < NB * 256; i += TPB) {
        int jj = i >> 8, t = i & 255;
        int b = min(base + jj, 1023);
        sm.sidx[jj][t] = s2[b * 256 + t];
    }
    if (gu) {
        int b = min(base + j, 1023);
        sm.gidx[j][hd] = l2[b * 64 + hd];
        __half hh = __float2half_rn(hinit);
        sm.hhi[j][hd] = hh;
        sm.hlo[j][hd] = __float2half_rn(hinit - __half2float(hh));
    }
    __syncthreads();

    c = cinit;
    run_lstm(tid, GXT[1], Whh2, &sm, c);
    __syncthreads();

    // ---------- FC head ----------
    for (int u = tid; u < NB * 128; u += TPB) {
        int jj = u >> 7, f = u & 127;
        const float* w = Wl1 + f * 64;
        float a = bl1[f];
        #pragma unroll
        for (int k = 0; k < 64; k++) a += w[k] * sm.gh[jj][k];
        sm.f1[jj][f] = tanhap(a);
    }
    __syncthreads();
    if (tid < NB * 4) {
        int jj = tid >> 2, o = tid & 3;
        const float* w = Wl2 + o * 128;
        float a = bl2[o];
        #pragma unroll 16
        for (int k = 0; k < 128; k++) a += w[k] * sm.f1[jj][k];
        int b = base + jj;
        if (b < 1024) out[b * 4 + o] = a;
    }
}

extern "C" void kernel_launch(void* const* d_in, const int* in_sizes, int n_in,
                              void* d_out, int out_size)
{
    // 0 s1, 1 s2, 2 s1_len, 3 s2_len, 4 s1_s, 5 s2_s, 6 emb,
    // 7 Wih1, 8 Whh1, 9 bih1, 10 bhh1, 11 Wih2, 12 Whh2, 13 bih2, 14 bhh2,
    // 15 Wl1, 16 bl1, 17 Wl2, 18 bl2
    precompute_gx<<<dim3(PCG, 2), 256>>>(
        (const float*)d_in[6],
        (const float*)d_in[7], (const float*)d_in[9], (const float*)d_in[10],
        (const float*)d_in[11], (const float*)d_in[13], (const float*)d_in[14]);

    cond_enc_kernel<<<GRID, TPB>>>(
        (const int*)d_in[0], (const int*)d_in[1],
        (const int*)d_in[2], (const int*)d_in[3],
        (const float*)d_in[8], (const float*)d_in[12],
        (const float*)d_in[15], (const float*)d_in[16],
        (const float*)d_in[17], (const float*)d_in[18],
        (float*)d_out);
}